// round 10
// baseline (speedup 1.0000x reference)
#include <cuda_runtime.h>
#include <cuda_fp16.h>
#include <math.h>
#include <stdint.h>

// Problem constants
#define NN     20000
#define NE     320000
#define HID    10
#define NIN    9
#define EF     11
#define NITER  7
#define ES     256      // edges per tile
#define TILES  (NE/ES)  // 1250
#define NTHR   512      // 16 warps
#define NCTA   152      // persistent CTAs

// ---------------- smem layout (byte offsets) -------------------------------
#define SA        200
#define OFF_A     0
#define A_BYTES   (ES*SA*2)              // 102400
#define SB1       40
#define OFF_B1    A_BYTES                // 102400
#define B1_BYTES  (96*SB1*2)             // 7680
#define SB2       104
#define OFF_B2    (OFF_B1 + B1_BYTES)    // 110080
#define B2_BYTES  (96*SB2*2)             // 19968
#define OFF_B3    (OFF_B2 + B2_BYTES)    // 130048
#define OFF_B4    (OFF_B3 + B2_BYTES)    // 150016
#define B4_BYTES  (16*SB2*2)             // 3328
#define OFF_BIAS  (OFF_B4 + B4_BYTES)    // 153344  (304 floats)
#define OFF_IDS   (OFF_BIAS + 304*4)     // 154560  (512 ints)
#define SMEM_REQ  (OFF_IDS + 512*4)      // 156608

// Weight blob (fp16 hi only): B1|B2|B3|B4
#define WB1_E   (96*SB1)                 // 3840
#define WB2_E   (96*SB2)                 // 9984
#define WB_ELEMS (WB1_E + 2*WB2_E + 16*SB2)   // 25472
__device__ __align__(16) uint16_t g_wb[WB_ELEMS];
__device__ float g_h[2][NN * HID];
__device__ float g_agg[NN * EF];
__device__ int   g_tctr[NITER];

// ------------------------------ helpers ------------------------------------
__device__ __forceinline__ uint32_t smem_u32(const void* p)
{
    uint32_t a;
    asm("{ .reg .u64 t; cvta.to.shared.u64 t, %1; cvt.u32.u64 %0, t; }"
        : "=r"(a) : "l"(p));
    return a;
}

__device__ __forceinline__ void ldsm_x4(uint32_t& r0, uint32_t& r1,
                                        uint32_t& r2, uint32_t& r3, uint32_t a)
{
    asm volatile("ldmatrix.sync.aligned.m8n8.x4.shared.b16 {%0,%1,%2,%3}, [%4];"
                 : "=r"(r0), "=r"(r1), "=r"(r2), "=r"(r3) : "r"(a));
}

__device__ __forceinline__ void ldsm_x2(uint32_t& r0, uint32_t& r1, uint32_t a)
{
    asm volatile("ldmatrix.sync.aligned.m8n8.x2.shared.b16 {%0,%1}, [%2];"
                 : "=r"(r0), "=r"(r1) : "r"(a));
}

__device__ __forceinline__ void mma_fp16(float& d0, float& d1, float& d2, float& d3,
                                         uint32_t a0, uint32_t a1, uint32_t a2,
                                         uint32_t a3, uint32_t b0, uint32_t b1)
{
    asm volatile(
        "mma.sync.aligned.m16n8k16.row.col.f32.f16.f16.f32 "
        "{%0,%1,%2,%3},{%4,%5,%6,%7},{%8,%9},{%0,%1,%2,%3};"
        : "+f"(d0), "+f"(d1), "+f"(d2), "+f"(d3)
        : "r"(a0), "r"(a1), "r"(a2), "r"(a3), "r"(b0), "r"(b1));
}

// fp16 hi/lo split of two floats (low half = first value)
__device__ __forceinline__ void pack_hilo(float a, float b, uint32_t& hw, uint32_t& lw)
{
    __half2 h2 = __floats2half2_rn(a, b);
    float ra = a - __half2float(__low2half(h2));
    float rb = b - __half2float(__high2half(h2));
    __half2 l2 = __floats2half2_rn(ra, rb);
    hw = *reinterpret_cast<uint32_t*>(&h2);
    lw = *reinterpret_cast<uint32_t*>(&l2);
}

// ---------------------------------------------------------------------------
// Setup: zero state + pack fp16(hi) weights (single kernel => launch parity
// puts edge_kernel at ncu's -s 5 slot)
// ---------------------------------------------------------------------------
__global__ void setup_kernel(const float* __restrict__ W1, const float* __restrict__ W2,
                             const float* __restrict__ W3, const float* __restrict__ W4)
{
    int i = blockIdx.x * blockDim.x + threadIdx.x;
    if (i < NN * HID) g_h[0][i] = 0.0f;
    if (i < NN * EF) g_agg[i] = 0.0f;
    if (i < NITER) g_tctr[i] = 0;
    if (i < WB_ELEMS) {
        const int E1 = WB1_E, E2 = E1 + WB2_E, E3 = E2 + WB2_E;
        const float* W; int e, stride, rows_real, k_real;
        if (i < E1)      { W = W1; e = i;      stride = SB1; rows_real = 96; k_real = 31; }
        else if (i < E2) { W = W2; e = i - E1; stride = SB2; rows_real = 96; k_real = 96; }
        else if (i < E3) { W = W3; e = i - E2; stride = SB2; rows_real = 96; k_real = 96; }
        else             { W = W4; e = i - E3; stride = SB2; rows_real = 11; k_real = 96; }
        int row = e / stride, c = e % stride;
        uint16_t bits = 0;
        if (row < rows_real && c < k_real) {
            __half h = __float2half_rn(W[row * k_real + c]);
            bits = *reinterpret_cast<uint16_t*>(&h);
        }
        g_wb[i] = bits;
    }
}

// ---------------------------------------------------------------------------
// One 96-wide layer, 2-pass fp16: D += (A_hi + A_lo) x B_hi^T
// B fragments hoisted: loaded once per k-step, used by both passes.
// ---------------------------------------------------------------------------
template<int KSTEPS, int SBB>
__device__ __forceinline__ void mma_layer(uint32_t sA, uint32_t sB,
                                          int cA_lo,
                                          int warp_m, int warp_n,
                                          int a_r, int a_k, int b_n, int b_k,
                                          float (&d)[2][6][4])
{
    uint32_t aHi = sA + (((warp_m * 32 + a_r) * SA + a_k) << 1);
    uint32_t aLo = aHi + (cA_lo << 1);
    uint32_t bBase = sB + (((warp_n * 48 + b_n) * SBB + b_k) << 1);
#pragma unroll
    for (int ks = 0; ks < KSTEPS; ks++) {
        uint32_t bb0[6], bb1[6];
#pragma unroll
        for (int j = 0; j < 3; j++) {
            uint32_t t0, t1, t2, t3;
            ldsm_x4(t0, t1, t2, t3, bBase + j * (16 * SBB * 2) + ks * 32);
            bb0[2 * j] = t0; bb1[2 * j] = t1;
            bb0[2 * j + 1] = t2; bb1[2 * j + 1] = t3;
        }
#pragma unroll
        for (int mi = 0; mi < 2; mi++) {
            uint32_t h0, h1, h2, h3, l0, l1, l2, l3;
            ldsm_x4(h0, h1, h2, h3, aHi + mi * (16 * SA * 2) + ks * 32);
            ldsm_x4(l0, l1, l2, l3, aLo + mi * (16 * SA * 2) + ks * 32);
#pragma unroll
            for (int ni = 0; ni < 6; ni++)
                mma_fp16(d[mi][ni][0], d[mi][ni][1], d[mi][ni][2], d[mi][ni][3],
                         h0, h1, h2, h3, bb0[ni], bb1[ni]);
#pragma unroll
            for (int ni = 0; ni < 6; ni++)
                mma_fp16(d[mi][ni][0], d[mi][ni][1], d[mi][ni][2], d[mi][ni][3],
                         l0, l1, l2, l3, bb0[ni], bb1[ni]);
        }
    }
}

__device__ __forceinline__ void store_act(char* sm, float (&d)[2][6][4],
                                          const float* bias, int boff,
                                          int warp_m, int warp_n, int lane)
{
    int g = lane >> 2, q = (lane & 3) * 2;
#pragma unroll
    for (int mi = 0; mi < 2; mi++) {
#pragma unroll
        for (int ni = 0; ni < 6; ni++) {
            int r0 = warp_m * 32 + mi * 16 + g;
            int c = warp_n * 48 + ni * 8 + q;
            float bz0 = bias[boff + c], bz1 = bias[boff + c + 1];
            float v0 = fmaxf(d[mi][ni][0] + bz0, 0.0f);
            float v1 = fmaxf(d[mi][ni][1] + bz1, 0.0f);
            float v2 = fmaxf(d[mi][ni][2] + bz0, 0.0f);
            float v3 = fmaxf(d[mi][ni][3] + bz1, 0.0f);
            uint32_t hw, lw;
            pack_hilo(v0, v1, hw, lw);
            *(uint32_t*)(sm + OFF_A + (r0 * SA + c) * 2) = hw;
            *(uint32_t*)(sm + OFF_A + (r0 * SA + 96 + c) * 2) = lw;
            pack_hilo(v2, v3, hw, lw);
            *(uint32_t*)(sm + OFF_A + ((r0 + 8) * SA + c) * 2) = hw;
            *(uint32_t*)(sm + OFF_A + ((r0 + 8) * SA + 96 + c) * 2) = lw;
        }
    }
}

// ---------------------------------------------------------------------------
// Persistent fused edge MLP (mma.sync fp16 2-pass) + scatter-add
// ---------------------------------------------------------------------------
__global__ __launch_bounds__(NTHR, 1)
void edge_kernel(int iter, int parity,
                 const float* __restrict__ edge_attr,
                 const int* __restrict__ src, const int* __restrict__ dst,
                 const float* __restrict__ b1, const float* __restrict__ b2,
                 const float* __restrict__ b3, const float* __restrict__ b4)
{
    extern __shared__ char sm[];
    const uint32_t sbase = smem_u32(sm);
    const int tid = threadIdx.x;
    const int wid = tid >> 5, lane = tid & 31;

    float* bias = (float*)(sm + OFF_BIAS);
    int* ids = (int*)(sm + OFF_IDS);
    __shared__ int s_tile;

    // stage weights + biases ONCE per CTA
    {
        const float4* gw = (const float4*)g_wb;
        float4* sw = (float4*)(sm + OFF_B1);
        for (int i = tid; i < WB_ELEMS / 8; i += NTHR) sw[i] = gw[i];
    }
    if (tid < 96) { bias[tid] = b1[tid]; bias[96 + tid] = b2[tid]; bias[192 + tid] = b3[tid]; }
    if (tid >= 96 && tid < 112) bias[288 + tid - 96] = (tid - 96 < EF) ? b4[tid - 96] : 0.0f;

    const int warp_m = wid & 7, warp_n = wid >> 3;
    const int am = lane >> 3;
    const int a_r = ((am & 1) << 3) | (lane & 7);
    const int a_k = (am >> 1) << 3;
    const int b_n = ((am >> 1) << 3) | (lane & 7);
    const int b_k = (am & 1) << 3;

    while (true) {
        if (tid == 0) s_tile = atomicAdd(&g_tctr[iter], 1);
        __syncthreads();
        const int tile = s_tile;
        if (tile >= TILES) break;
        const int ebase = tile * ES;

        ids[tid] = (tid < 256) ? src[ebase + tid] : dst[ebase + tid - 256];
        __syncthreads();

        // gather: 2 threads per row (cols 0..15 / 16..31), hi + lo
        {
            int row = tid >> 1, half = tid & 1;
            float x[16];
            if (half == 0) {
                const float* hs = g_h[parity] + (size_t)ids[row] * HID;
                const float* hd = g_h[parity] + (size_t)ids[256 + row] * HID;
#pragma unroll
                for (int i = 0; i < HID; i++) x[i] = hs[i];
#pragma unroll
                for (int i = 0; i < 6; i++) x[HID + i] = hd[i];
            } else {
                const float* hd = g_h[parity] + (size_t)ids[256 + row] * HID;
#pragma unroll
                for (int i = 0; i < 4; i++) x[i] = hd[6 + i];
#pragma unroll
                for (int i = 0; i < EF; i++)
                    x[4 + i] = edge_attr[(size_t)(ebase + row) * EF + i];
                x[15] = 0.0f;
            }
            int cb = half * 16;
#pragma unroll
            for (int p = 0; p < 8; p++) {
                uint32_t hw, lw;
                pack_hilo(x[2 * p], x[2 * p + 1], hw, lw);
                *(uint32_t*)(sm + OFF_A + (row * SA + cb + 2 * p) * 2) = hw;
                *(uint32_t*)(sm + OFF_A + (row * SA + 32 + cb + 2 * p) * 2) = lw;
            }
        }
        __syncthreads();

        float d[2][6][4];

        // ---- Layer 1 (K=32 incl pad, A lo at col 32)
#pragma unroll
        for (int mi = 0; mi < 2; mi++)
#pragma unroll
            for (int ni = 0; ni < 6; ni++)
#pragma unroll
                for (int v = 0; v < 4; v++) d[mi][ni][v] = 0.0f;
        mma_layer<2, SB1>(sbase + OFF_A, sbase + OFF_B1, 32,
                          warp_m, warp_n, a_r, a_k, b_n, b_k, d);
        __syncthreads();
        store_act(sm, d, bias, 0, warp_m, warp_n, lane);
        __syncthreads();

        // ---- Layer 2
#pragma unroll
        for (int mi = 0; mi < 2; mi++)
#pragma unroll
            for (int ni = 0; ni < 6; ni++)
#pragma unroll
                for (int v = 0; v < 4; v++) d[mi][ni][v] = 0.0f;
        mma_layer<6, SB2>(sbase + OFF_A, sbase + OFF_B2, 96,
                          warp_m, warp_n, a_r, a_k, b_n, b_k, d);
        __syncthreads();
        store_act(sm, d, bias, 96, warp_m, warp_n, lane);
        __syncthreads();

        // ---- Layer 3
#pragma unroll
        for (int mi = 0; mi < 2; mi++)
#pragma unroll
            for (int ni = 0; ni < 6; ni++)
#pragma unroll
                for (int v = 0; v < 4; v++) d[mi][ni][v] = 0.0f;
        mma_layer<6, SB2>(sbase + OFF_A, sbase + OFF_B3, 96,
                          warp_m, warp_n, a_r, a_k, b_n, b_k, d);
        __syncthreads();
        store_act(sm, d, bias, 192, warp_m, warp_n, lane);
        __syncthreads();

        // ---- Layer 4: N=16 (11 real)
        float d4[2][4];
#pragma unroll
        for (int mi = 0; mi < 2; mi++)
#pragma unroll
            for (int v = 0; v < 4; v++) d4[mi][v] = 0.0f;
        {
            const int b4n = (lane & 7);
            const int b4k = ((lane >> 3) & 1) * 8;
            uint32_t aHi = sbase + OFF_A + (((warp_m * 32 + a_r) * SA + a_k) << 1);
            uint32_t aLo = aHi + (96 << 1);
            uint32_t bBase = sbase + OFF_B4 + (((warp_n * 8 + b4n) * SB2 + b4k) << 1);
#pragma unroll
            for (int ks = 0; ks < 6; ks++) {
                uint32_t bb0, bb1;
                ldsm_x2(bb0, bb1, bBase + ks * 32);
#pragma unroll
                for (int mi = 0; mi < 2; mi++) {
                    uint32_t h0, h1, h2, h3, l0, l1, l2, l3;
                    ldsm_x4(h0, h1, h2, h3, aHi + mi * (16 * SA * 2) + ks * 32);
                    ldsm_x4(l0, l1, l2, l3, aLo + mi * (16 * SA * 2) + ks * 32);
                    mma_fp16(d4[mi][0], d4[mi][1], d4[mi][2], d4[mi][3],
                             h0, h1, h2, h3, bb0, bb1);
                    mma_fp16(d4[mi][0], d4[mi][1], d4[mi][2], d4[mi][3],
                             l0, l1, l2, l3, bb0, bb1);
                }
            }
        }

        // scatter-add
        {
            int g = lane >> 2, q = (lane & 3) * 2;
            int c = warp_n * 8 + q;
            float bz0 = (c < EF) ? bias[288 + c] : 0.0f;
            float bz1 = (c + 1 < EF) ? bias[288 + c + 1] : 0.0f;
#pragma unroll
            for (int mi = 0; mi < 2; mi++) {
                int r = warp_m * 32 + mi * 16 + g;
                int dn0 = ids[256 + r];
                int dn1 = ids[256 + r + 8];
                if (c < EF) {
                    atomicAdd(&g_agg[(size_t)dn0 * EF + c], d4[mi][0] + bz0);
                    atomicAdd(&g_agg[(size_t)dn1 * EF + c], d4[mi][2] + bz0);
                }
                if (c + 1 < EF) {
                    atomicAdd(&g_agg[(size_t)dn0 * EF + c + 1], d4[mi][1] + bz1);
                    atomicAdd(&g_agg[(size_t)dn1 * EF + c + 1], d4[mi][3] + bz1);
                }
            }
        }
    }
}

// ---------------------------------------------------------------------------
// GRU cell + output head; zeroes g_agg for next iter.
// ---------------------------------------------------------------------------
__global__ void gru_kernel(int parity,
                           const float* __restrict__ node_in,
                           const float* __restrict__ wih,
                           const float* __restrict__ whh,
                           const float* __restrict__ bih,
                           const float* __restrict__ bhh,
                           const float* __restrict__ fw,
                           const float* __restrict__ fb,
                           float* __restrict__ out)
{
    __shared__ float s[600 + 300 + 30 + 30 + 20 + 2];
    int tid = threadIdx.x;
    for (int i = tid; i < 600; i += blockDim.x) s[i] = wih[i];
    for (int i = tid; i < 300; i += blockDim.x) s[600 + i] = whh[i];
    for (int i = tid; i < 30; i += blockDim.x) { s[900 + i] = bih[i]; s[930 + i] = bhh[i]; }
    for (int i = tid; i < 20; i += blockDim.x) s[960 + i] = fw[i];
    for (int i = tid; i < 2; i += blockDim.x) s[980 + i] = fb[i];
    __syncthreads();

    int n = blockIdx.x * blockDim.x + tid;
    if (n >= NN) return;

    const float* __restrict__ hp = g_h[parity] + n * HID;
    float* __restrict__ hn = g_h[1 - parity] + n * HID;

    float x[20], hv[HID];
#pragma unroll
    for (int i = 0; i < EF; i++) { x[i] = g_agg[n * EF + i]; g_agg[n * EF + i] = 0.0f; }
#pragma unroll
    for (int i = 0; i < NIN; i++) x[EF + i] = node_in[n * NIN + i];
#pragma unroll
    for (int i = 0; i < HID; i++) hv[i] = hp[i];

    float gi[30], gh[30];
#pragma unroll
    for (int g = 0; g < 30; g++) {
        float a = s[900 + g];
#pragma unroll
        for (int k = 0; k < 20; k++) a = fmaf(s[g * 20 + k], x[k], a);
        gi[g] = a;
        float b = s[930 + g];
#pragma unroll
        for (int k = 0; k < 10; k++) b = fmaf(s[600 + g * 10 + k], hv[k], b);
        gh[g] = b;
    }

    float hnew[HID];
#pragma unroll
    for (int i = 0; i < HID; i++) {
        float r = 1.0f / (1.0f + expf(-(gi[i] + gh[i])));
        float z = 1.0f / (1.0f + expf(-(gi[10 + i] + gh[10 + i])));
        float nval = tanhf(gi[20 + i] + r * gh[20 + i]);
        float hni = (1.0f - z) * nval + z * hv[i];
        hnew[i] = hni;
        hn[i] = hni;
    }

#pragma unroll
    for (int o = 0; o < 2; o++) {
        float a = s[980 + o];
#pragma unroll
        for (int k = 0; k < HID; k++) a = fmaf(s[960 + o * 10 + k], hnew[k], a);
        out[n * 2 + o] = a;
    }
}

// ---------------------------------------------------------------------------
// Launch
// ---------------------------------------------------------------------------
extern "C" void kernel_launch(void* const* d_in, const int* in_sizes, int n_in,
                              void* d_out, int out_size)
{
    const float* node_in   = (const float*)d_in[0];
    const float* edge_attr = (const float*)d_in[1];
    const float* W1 = (const float*)d_in[2];  const float* b1 = (const float*)d_in[3];
    const float* W2 = (const float*)d_in[4];  const float* b2 = (const float*)d_in[5];
    const float* W3 = (const float*)d_in[6];  const float* b3 = (const float*)d_in[7];
    const float* W4 = (const float*)d_in[8];  const float* b4 = (const float*)d_in[9];
    const float* wih = (const float*)d_in[10]; const float* whh = (const float*)d_in[11];
    const float* bih = (const float*)d_in[12]; const float* bhh = (const float*)d_in[13];
    const float* fw  = (const float*)d_in[14]; const float* fb  = (const float*)d_in[15];
    const int* src = (const int*)d_in[16];
    const int* dst = (const int*)d_in[17];
    float* out = (float*)d_out;

    cudaFuncSetAttribute(edge_kernel,
                         cudaFuncAttributeMaxDynamicSharedMemorySize, SMEM_REQ);

    setup_kernel<<<(NN * EF + 255) / 256, 256>>>(W1, W2, W3, W4);

    for (int t = 0; t < NITER; t++) {
        int p = t & 1;
        edge_kernel<<<NCTA, NTHR, SMEM_REQ>>>(t, p, edge_attr, src, dst,
                                              b1, b2, b3, b4);
        gru_kernel<<<(NN + 127) / 128, 128>>>(p, node_in, wih, whh, bih, bhh,
                                              fw, fb, out + (size_t)t * NN * 2);
    }
}

// round 12
// speedup vs baseline: 1.6261x; 1.6261x over previous
#include <cuda_runtime.h>
#include <cuda_fp16.h>
#include <math.h>
#include <stdint.h>

// Problem constants
#define NN     20000
#define NE     320000
#define HID    10
#define NIN    9
#define EF     11
#define NITER  7
#define EST    128       // edges per half-tile
#define TILES2 (NE/EST)  // 2500
#define NTHR   512       // 16 warps = 2 halves x 8 warps
#define NCTA   152       // persistent CTAs

// ---------------- smem layout (byte offsets) -------------------------------
#define SA        200
#define OFF_A     0
#define A_BYTES   (256*SA*2)             // 102400 (two 128-row halves)
#define SB1       40
#define OFF_B1    A_BYTES                // 102400
#define B1_BYTES  (96*SB1*2)             // 7680
#define SB2       104
#define OFF_B2    (OFF_B1 + B1_BYTES)    // 110080
#define B2_BYTES  (96*SB2*2)             // 19968
#define OFF_B3    (OFF_B2 + B2_BYTES)    // 130048
#define OFF_B4    (OFF_B3 + B2_BYTES)    // 150016
#define B4_BYTES  (16*SB2*2)             // 3328
#define OFF_BIAS  (OFF_B4 + B4_BYTES)    // 153344  (304 floats)
#define OFF_IDS   (OFF_BIAS + 304*4)     // 154560  (2 x 256 ints)
#define SMEM_REQ  (OFF_IDS + 512*4)      // 156608

// Weight blob (fp16 hi only): B1|B2|B3|B4
#define WB1_E   (96*SB1)                 // 3840
#define WB2_E   (96*SB2)                 // 9984
#define WB_ELEMS (WB1_E + 2*WB2_E + 16*SB2)   // 25472
__device__ __align__(16) uint16_t g_wb[WB_ELEMS];
__device__ float g_h[2][NN * HID];
__device__ float g_agg[NN * EF];
__device__ int   g_tctr[NITER];

// ------------------------------ helpers ------------------------------------
__device__ __forceinline__ uint32_t smem_u32(const void* p)
{
    uint32_t a;
    asm("{ .reg .u64 t; cvta.to.shared.u64 t, %1; cvt.u32.u64 %0, t; }"
        : "=r"(a) : "l"(p));
    return a;
}

__device__ __forceinline__ void barh(int id)
{
    asm volatile("bar.sync %0, 256;" :: "r"(id) : "memory");
}

__device__ __forceinline__ void ldsm_x4(uint32_t& r0, uint32_t& r1,
                                        uint32_t& r2, uint32_t& r3, uint32_t a)
{
    asm volatile("ldmatrix.sync.aligned.m8n8.x4.shared.b16 {%0,%1,%2,%3}, [%4];"
                 : "=r"(r0), "=r"(r1), "=r"(r2), "=r"(r3) : "r"(a));
}

__device__ __forceinline__ void ldsm_x2(uint32_t& r0, uint32_t& r1, uint32_t a)
{
    asm volatile("ldmatrix.sync.aligned.m8n8.x2.shared.b16 {%0,%1}, [%2];"
                 : "=r"(r0), "=r"(r1) : "r"(a));
}

__device__ __forceinline__ void mma_fp16(float& d0, float& d1, float& d2, float& d3,
                                         uint32_t a0, uint32_t a1, uint32_t a2,
                                         uint32_t a3, uint32_t b0, uint32_t b1)
{
    asm volatile(
        "mma.sync.aligned.m16n8k16.row.col.f32.f16.f16.f32 "
        "{%0,%1,%2,%3},{%4,%5,%6,%7},{%8,%9},{%0,%1,%2,%3};"
        : "+f"(d0), "+f"(d1), "+f"(d2), "+f"(d3)
        : "r"(a0), "r"(a1), "r"(a2), "r"(a3), "r"(b0), "r"(b1));
}

// fp16 hi/lo split of two floats (low half = first value)
__device__ __forceinline__ void pack_hilo(float a, float b, uint32_t& hw, uint32_t& lw)
{
    __half2 h2 = __floats2half2_rn(a, b);
    float ra = a - __half2float(__low2half(h2));
    float rb = b - __half2float(__high2half(h2));
    __half2 l2 = __floats2half2_rn(ra, rb);
    hw = *reinterpret_cast<uint32_t*>(&h2);
    lw = *reinterpret_cast<uint32_t*>(&l2);
}

// ---------------------------------------------------------------------------
// Setup: zero state + pack fp16(hi) weights
// ---------------------------------------------------------------------------
__global__ void setup_kernel(const float* __restrict__ W1, const float* __restrict__ W2,
                             const float* __restrict__ W3, const float* __restrict__ W4)
{
    int i = blockIdx.x * blockDim.x + threadIdx.x;
    if (i < NN * HID) g_h[0][i] = 0.0f;
    if (i < NN * EF) g_agg[i] = 0.0f;
    if (i < NITER) g_tctr[i] = 0;
    if (i < WB_ELEMS) {
        const int E1 = WB1_E, E2 = E1 + WB2_E, E3 = E2 + WB2_E;
        const float* W; int e, stride, rows_real, k_real;
        if (i < E1)      { W = W1; e = i;      stride = SB1; rows_real = 96; k_real = 31; }
        else if (i < E2) { W = W2; e = i - E1; stride = SB2; rows_real = 96; k_real = 96; }
        else if (i < E3) { W = W3; e = i - E2; stride = SB2; rows_real = 96; k_real = 96; }
        else             { W = W4; e = i - E3; stride = SB2; rows_real = 11; k_real = 96; }
        int row = e / stride, c = e % stride;
        uint16_t bits = 0;
        if (row < rows_real && c < k_real) {
            __half h = __float2half_rn(W[row * k_real + c]);
            bits = *reinterpret_cast<uint16_t*>(&h);
        }
        g_wb[i] = bits;
    }
}

// ---------------------------------------------------------------------------
// One 96-wide layer, 2-pass fp16: D += (A_hi + A_lo) x B_hi^T
// Half-tile: 128 rows; warp tile 32 rows x 48 cols.
// ---------------------------------------------------------------------------
template<int KSTEPS, int SBB>
__device__ __forceinline__ void mma_layer(uint32_t sA, uint32_t sB,
                                          int cA_lo,
                                          int warp_m, int warp_n,
                                          int a_r, int a_k, int b_n, int b_k,
                                          float (&d)[2][6][4])
{
    uint32_t aHi = sA + (((warp_m * 32 + a_r) * SA + a_k) << 1);
    uint32_t aLo = aHi + (cA_lo << 1);
    uint32_t bBase = sB + (((warp_n * 48 + b_n) * SBB + b_k) << 1);
#pragma unroll
    for (int ks = 0; ks < KSTEPS; ks++) {
        uint32_t bb0[6], bb1[6];
#pragma unroll
        for (int j = 0; j < 3; j++) {
            uint32_t t0, t1, t2, t3;
            ldsm_x4(t0, t1, t2, t3, bBase + j * (16 * SBB * 2) + ks * 32);
            bb0[2 * j] = t0; bb1[2 * j] = t1;
            bb0[2 * j + 1] = t2; bb1[2 * j + 1] = t3;
        }
#pragma unroll
        for (int mi = 0; mi < 2; mi++) {
            uint32_t h0, h1, h2, h3, l0, l1, l2, l3;
            ldsm_x4(h0, h1, h2, h3, aHi + mi * (16 * SA * 2) + ks * 32);
            ldsm_x4(l0, l1, l2, l3, aLo + mi * (16 * SA * 2) + ks * 32);
#pragma unroll
            for (int ni = 0; ni < 6; ni++)
                mma_fp16(d[mi][ni][0], d[mi][ni][1], d[mi][ni][2], d[mi][ni][3],
                         h0, h1, h2, h3, bb0[ni], bb1[ni]);
#pragma unroll
            for (int ni = 0; ni < 6; ni++)
                mma_fp16(d[mi][ni][0], d[mi][ni][1], d[mi][ni][2], d[mi][ni][3],
                         l0, l1, l2, l3, bb0[ni], bb1[ni]);
        }
    }
}

__device__ __forceinline__ void store_act(char* smA, float (&d)[2][6][4],
                                          const float* bias, int boff,
                                          int warp_m, int warp_n, int lane)
{
    int g = lane >> 2, q = (lane & 3) * 2;
#pragma unroll
    for (int mi = 0; mi < 2; mi++) {
#pragma unroll
        for (int ni = 0; ni < 6; ni++) {
            int r0 = warp_m * 32 + mi * 16 + g;
            int c = warp_n * 48 + ni * 8 + q;
            float bz0 = bias[boff + c], bz1 = bias[boff + c + 1];
            float v0 = fmaxf(d[mi][ni][0] + bz0, 0.0f);
            float v1 = fmaxf(d[mi][ni][1] + bz1, 0.0f);
            float v2 = fmaxf(d[mi][ni][2] + bz0, 0.0f);
            float v3 = fmaxf(d[mi][ni][3] + bz1, 0.0f);
            uint32_t hw, lw;
            pack_hilo(v0, v1, hw, lw);
            *(uint32_t*)(smA + (r0 * SA + c) * 2) = hw;
            *(uint32_t*)(smA + (r0 * SA + 96 + c) * 2) = lw;
            pack_hilo(v2, v3, hw, lw);
            *(uint32_t*)(smA + ((r0 + 8) * SA + c) * 2) = hw;
            *(uint32_t*)(smA + ((r0 + 8) * SA + 96 + c) * 2) = lw;
        }
    }
}

// ---------------------------------------------------------------------------
// Persistent fused edge MLP: 2 independent 8-warp pipelines per CTA
// ---------------------------------------------------------------------------
__global__ __launch_bounds__(NTHR, 1)
void edge_kernel(int iter, int parity,
                 const float* __restrict__ edge_attr,
                 const int* __restrict__ src, const int* __restrict__ dst,
                 const float* __restrict__ b1, const float* __restrict__ b2,
                 const float* __restrict__ b3, const float* __restrict__ b4)
{
    extern __shared__ char sm[];
    const uint32_t sbase = smem_u32(sm);
    const int tid = threadIdx.x;

    float* bias = (float*)(sm + OFF_BIAS);
    __shared__ int s_tile[2];

    // stage weights + biases ONCE per CTA (all 512 threads)
    {
        const float4* gw = (const float4*)g_wb;
        float4* sw = (float4*)(sm + OFF_B1);
        for (int i = tid; i < WB_ELEMS / 8; i += NTHR) sw[i] = gw[i];
    }
    if (tid < 96) { bias[tid] = b1[tid]; bias[96 + tid] = b2[tid]; bias[192 + tid] = b3[tid]; }
    if (tid >= 96 && tid < 112) bias[288 + tid - 96] = (tid - 96 < EF) ? b4[tid - 96] : 0.0f;
    __syncthreads();

    // split into two independent halves
    const int half = tid >> 8;          // 0 / 1
    const int htid = tid & 255;
    const int hwid = htid >> 5;         // 0..7
    const int lane = htid & 31;
    const int bar_id = 1 + half;

    const int warp_m = hwid & 3;        // 4 x 32 rows
    const int warp_n = hwid >> 2;       // 2 x 48 cols
    const int am = lane >> 3;
    const int a_r = ((am & 1) << 3) | (lane & 7);
    const int a_k = (am >> 1) << 3;
    const int b_n = ((am >> 1) << 3) | (lane & 7);
    const int b_k = (am & 1) << 3;

    char* smA = sm + OFF_A + half * (EST * SA * 2);
    const uint32_t sbA = sbase + OFF_A + half * (EST * SA * 2);
    int* ids = (int*)(sm + OFF_IDS) + half * 256;

    while (true) {
        if (htid == 0) s_tile[half] = atomicAdd(&g_tctr[iter], 1);
        barh(bar_id);                    // also: half done with previous tile
        const int tile = s_tile[half];
        if (tile >= TILES2) break;
        const int ebase = tile * EST;

        ids[htid] = (htid < EST) ? src[ebase + htid] : dst[ebase + htid - EST];
        barh(bar_id);

        // gather: 2 threads per row (cols 0..15 / 16..31), hi + lo
        {
            int row = htid >> 1, hf = htid & 1;
            float x[16];
            if (hf == 0) {
                const float* hs = g_h[parity] + (size_t)ids[row] * HID;
                const float* hd = g_h[parity] + (size_t)ids[EST + row] * HID;
#pragma unroll
                for (int i = 0; i < HID; i++) x[i] = hs[i];
#pragma unroll
                for (int i = 0; i < 6; i++) x[HID + i] = hd[i];
            } else {
                const float* hd = g_h[parity] + (size_t)ids[EST + row] * HID;
#pragma unroll
                for (int i = 0; i < 4; i++) x[i] = hd[6 + i];
#pragma unroll
                for (int i = 0; i < EF; i++)
                    x[4 + i] = edge_attr[(size_t)(ebase + row) * EF + i];
                x[15] = 0.0f;
            }
            int cb = hf * 16;
#pragma unroll
            for (int p = 0; p < 8; p++) {
                uint32_t hw, lw;
                pack_hilo(x[2 * p], x[2 * p + 1], hw, lw);
                *(uint32_t*)(smA + (row * SA + cb + 2 * p) * 2) = hw;
                *(uint32_t*)(smA + (row * SA + 32 + cb + 2 * p) * 2) = lw;
            }
        }
        barh(bar_id);

        float d[2][6][4];

        // ---- Layer 1 (K=32 incl pad, A lo at col 32)
#pragma unroll
        for (int mi = 0; mi < 2; mi++)
#pragma unroll
            for (int ni = 0; ni < 6; ni++)
#pragma unroll
                for (int v = 0; v < 4; v++) d[mi][ni][v] = 0.0f;
        mma_layer<2, SB1>(sbA, sbase + OFF_B1, 32,
                          warp_m, warp_n, a_r, a_k, b_n, b_k, d);
        barh(bar_id);
        store_act(smA, d, bias, 0, warp_m, warp_n, lane);
        barh(bar_id);

        // ---- Layer 2
#pragma unroll
        for (int mi = 0; mi < 2; mi++)
#pragma unroll
            for (int ni = 0; ni < 6; ni++)
#pragma unroll
                for (int v = 0; v < 4; v++) d[mi][ni][v] = 0.0f;
        mma_layer<6, SB2>(sbA, sbase + OFF_B2, 96,
                          warp_m, warp_n, a_r, a_k, b_n, b_k, d);
        barh(bar_id);
        store_act(smA, d, bias, 96, warp_m, warp_n, lane);
        barh(bar_id);

        // ---- Layer 3
#pragma unroll
        for (int mi = 0; mi < 2; mi++)
#pragma unroll
            for (int ni = 0; ni < 6; ni++)
#pragma unroll
                for (int v = 0; v < 4; v++) d[mi][ni][v] = 0.0f;
        mma_layer<6, SB2>(sbA, sbase + OFF_B3, 96,
                          warp_m, warp_n, a_r, a_k, b_n, b_k, d);
        barh(bar_id);
        store_act(smA, d, bias, 192, warp_m, warp_n, lane);
        barh(bar_id);

        // ---- Layer 4: N=16 (11 real)
        float d4[2][4];
#pragma unroll
        for (int mi = 0; mi < 2; mi++)
#pragma unroll
            for (int v = 0; v < 4; v++) d4[mi][v] = 0.0f;
        {
            const int b4n = (lane & 7);
            const int b4k = ((lane >> 3) & 1) * 8;
            uint32_t aHi = sbA + (((warp_m * 32 + a_r) * SA + a_k) << 1);
            uint32_t aLo = aHi + (96 << 1);
            uint32_t bBase = sbase + OFF_B4 + (((warp_n * 8 + b4n) * SB2 + b4k) << 1);
#pragma unroll
            for (int ks = 0; ks < 6; ks++) {
                uint32_t bb0, bb1;
                ldsm_x2(bb0, bb1, bBase + ks * 32);
#pragma unroll
                for (int mi = 0; mi < 2; mi++) {
                    uint32_t h0, h1, h2, h3, l0, l1, l2, l3;
                    ldsm_x4(h0, h1, h2, h3, aHi + mi * (16 * SA * 2) + ks * 32);
                    ldsm_x4(l0, l1, l2, l3, aLo + mi * (16 * SA * 2) + ks * 32);
                    mma_fp16(d4[mi][0], d4[mi][1], d4[mi][2], d4[mi][3],
                             h0, h1, h2, h3, bb0, bb1);
                    mma_fp16(d4[mi][0], d4[mi][1], d4[mi][2], d4[mi][3],
                             l0, l1, l2, l3, bb0, bb1);
                }
            }
        }

        // scatter-add
        {
            int g = lane >> 2, q = (lane & 3) * 2;
            int c = warp_n * 8 + q;
            float bz0 = (c < EF) ? bias[288 + c] : 0.0f;
            float bz1 = (c + 1 < EF) ? bias[288 + c + 1] : 0.0f;
#pragma unroll
            for (int mi = 0; mi < 2; mi++) {
                int r = warp_m * 32 + mi * 16 + g;
                int dn0 = ids[EST + r];
                int dn1 = ids[EST + r + 8];
                if (c < EF) {
                    atomicAdd(&g_agg[(size_t)dn0 * EF + c], d4[mi][0] + bz0);
                    atomicAdd(&g_agg[(size_t)dn1 * EF + c], d4[mi][2] + bz0);
                }
                if (c + 1 < EF) {
                    atomicAdd(&g_agg[(size_t)dn0 * EF + c + 1], d4[mi][1] + bz1);
                    atomicAdd(&g_agg[(size_t)dn1 * EF + c + 1], d4[mi][3] + bz1);
                }
            }
        }
    }
}

// ---------------------------------------------------------------------------
// GRU cell + output head; zeroes g_agg for next iter.
// ---------------------------------------------------------------------------
__global__ void gru_kernel(int parity,
                           const float* __restrict__ node_in,
                           const float* __restrict__ wih,
                           const float* __restrict__ whh,
                           const float* __restrict__ bih,
                           const float* __restrict__ bhh,
                           const float* __restrict__ fw,
                           const float* __restrict__ fb,
                           float* __restrict__ out)
{
    __shared__ float s[600 + 300 + 30 + 30 + 20 + 2];
    int tid = threadIdx.x;
    for (int i = tid; i < 600; i += blockDim.x) s[i] = wih[i];
    for (int i = tid; i < 300; i += blockDim.x) s[600 + i] = whh[i];
    for (int i = tid; i < 30; i += blockDim.x) { s[900 + i] = bih[i]; s[930 + i] = bhh[i]; }
    for (int i = tid; i < 20; i += blockDim.x) s[960 + i] = fw[i];
    for (int i = tid; i < 2; i += blockDim.x) s[980 + i] = fb[i];
    __syncthreads();

    int n = blockIdx.x * blockDim.x + tid;
    if (n >= NN) return;

    const float* __restrict__ hp = g_h[parity] + n * HID;
    float* __restrict__ hn = g_h[1 - parity] + n * HID;

    float x[20], hv[HID];
#pragma unroll
    for (int i = 0; i < EF; i++) { x[i] = g_agg[n * EF + i]; g_agg[n * EF + i] = 0.0f; }
#pragma unroll
    for (int i = 0; i < NIN; i++) x[EF + i] = node_in[n * NIN + i];
#pragma unroll
    for (int i = 0; i < HID; i++) hv[i] = hp[i];

    float gi[30], gh[30];
#pragma unroll
    for (int g = 0; g < 30; g++) {
        float a = s[900 + g];
#pragma unroll
        for (int k = 0; k < 20; k++) a = fmaf(s[g * 20 + k], x[k], a);
        gi[g] = a;
        float b = s[930 + g];
#pragma unroll
        for (int k = 0; k < 10; k++) b = fmaf(s[600 + g * 10 + k], hv[k], b);
        gh[g] = b;
    }

    float hnew[HID];
#pragma unroll
    for (int i = 0; i < HID; i++) {
        float r = 1.0f / (1.0f + expf(-(gi[i] + gh[i])));
        float z = 1.0f / (1.0f + expf(-(gi[10 + i] + gh[10 + i])));
        float nval = tanhf(gi[20 + i] + r * gh[20 + i]);
        float hni = (1.0f - z) * nval + z * hv[i];
        hnew[i] = hni;
        hn[i] = hni;
    }

#pragma unroll
    for (int o = 0; o < 2; o++) {
        float a = s[980 + o];
#pragma unroll
        for (int k = 0; k < HID; k++) a = fmaf(s[960 + o * 10 + k], hnew[k], a);
        out[n * 2 + o] = a;
    }
}

// ---------------------------------------------------------------------------
// Launch
// ---------------------------------------------------------------------------
extern "C" void kernel_launch(void* const* d_in, const int* in_sizes, int n_in,
                              void* d_out, int out_size)
{
    const float* node_in   = (const float*)d_in[0];
    const float* edge_attr = (const float*)d_in[1];
    const float* W1 = (const float*)d_in[2];  const float* b1 = (const float*)d_in[3];
    const float* W2 = (const float*)d_in[4];  const float* b2 = (const float*)d_in[5];
    const float* W3 = (const float*)d_in[6];  const float* b3 = (const float*)d_in[7];
    const float* W4 = (const float*)d_in[8];  const float* b4 = (const float*)d_in[9];
    const float* wih = (const float*)d_in[10]; const float* whh = (const float*)d_in[11];
    const float* bih = (const float*)d_in[12]; const float* bhh = (const float*)d_in[13];
    const float* fw  = (const float*)d_in[14]; const float* fb  = (const float*)d_in[15];
    const int* src = (const int*)d_in[16];
    const int* dst = (const int*)d_in[17];
    float* out = (float*)d_out;

    cudaFuncSetAttribute(edge_kernel,
                         cudaFuncAttributeMaxDynamicSharedMemorySize, SMEM_REQ);

    setup_kernel<<<(NN * EF + 255) / 256, 256>>>(W1, W2, W3, W4);

    for (int t = 0; t < NITER; t++) {
        int p = t & 1;
        edge_kernel<<<NCTA, NTHR, SMEM_REQ>>>(t, p, edge_attr, src, dst,
                                              b1, b2, b3, b4);
        gru_kernel<<<(NN + 127) / 128, 128>>>(p, node_in, wih, whh, bih, bhh,
                                              fw, fb, out + (size_t)t * NN * 2);
    }
}

// round 13
// speedup vs baseline: 1.8742x; 1.1526x over previous
#include <cuda_runtime.h>
#include <cuda_fp16.h>
#include <math.h>
#include <stdint.h>

// Problem constants
#define NN     20000
#define NE     320000
#define HID    10
#define NIN    9
#define EF     11
#define NITER  7
#define EST    64        // edges per stream-tile
#define TILES4 (NE/EST)  // 5000
#define NTHR   512       // 16 warps = 4 streams x 4 warps
#define NCTA   152       // persistent CTAs

// ---------------- smem layout (byte offsets) -------------------------------
#define SA        200
#define OFF_A     0
#define A_BYTES   (256*SA*2)             // 102400 (4 x 64-row stream regions)
#define SB1       40
#define OFF_B1    A_BYTES                // 102400
#define B1_BYTES  (96*SB1*2)             // 7680
#define SB2       104
#define OFF_B2    (OFF_B1 + B1_BYTES)    // 110080
#define B2_BYTES  (96*SB2*2)             // 19968
#define OFF_B3    (OFF_B2 + B2_BYTES)    // 130048
#define OFF_B4    (OFF_B3 + B2_BYTES)    // 150016
#define B4_BYTES  (16*SB2*2)             // 3328
#define OFF_BIAS  (OFF_B4 + B4_BYTES)    // 153344  (304 floats)
#define OFF_IDS   (OFF_BIAS + 304*4)     // 154560  (4 x 128 ints)
#define SMEM_REQ  (OFF_IDS + 512*4)      // 156608

// Weight blob (fp16 hi only): B1|B2|B3|B4
#define WB1_E   (96*SB1)                 // 3840
#define WB2_E   (96*SB2)                 // 9984
#define WB_ELEMS (WB1_E + 2*WB2_E + 16*SB2)   // 25472
__device__ __align__(16) uint16_t g_wb[WB_ELEMS];
__device__ float g_h[2][NN * HID];
__device__ float g_agg[NN * EF];
__device__ int   g_tctr[NITER];

// ------------------------------ helpers ------------------------------------
__device__ __forceinline__ uint32_t smem_u32(const void* p)
{
    uint32_t a;
    asm("{ .reg .u64 t; cvta.to.shared.u64 t, %1; cvt.u32.u64 %0, t; }"
        : "=r"(a) : "l"(p));
    return a;
}

__device__ __forceinline__ void barq(int id)
{
    asm volatile("bar.sync %0, 128;" :: "r"(id) : "memory");
}

__device__ __forceinline__ void ldsm_x4(uint32_t& r0, uint32_t& r1,
                                        uint32_t& r2, uint32_t& r3, uint32_t a)
{
    asm volatile("ldmatrix.sync.aligned.m8n8.x4.shared.b16 {%0,%1,%2,%3}, [%4];"
                 : "=r"(r0), "=r"(r1), "=r"(r2), "=r"(r3) : "r"(a));
}

__device__ __forceinline__ void ldsm_x2(uint32_t& r0, uint32_t& r1, uint32_t a)
{
    asm volatile("ldmatrix.sync.aligned.m8n8.x2.shared.b16 {%0,%1}, [%2];"
                 : "=r"(r0), "=r"(r1) : "r"(a));
}

__device__ __forceinline__ void mma_fp16(float& d0, float& d1, float& d2, float& d3,
                                         uint32_t a0, uint32_t a1, uint32_t a2,
                                         uint32_t a3, uint32_t b0, uint32_t b1)
{
    asm volatile(
        "mma.sync.aligned.m16n8k16.row.col.f32.f16.f16.f32 "
        "{%0,%1,%2,%3},{%4,%5,%6,%7},{%8,%9},{%0,%1,%2,%3};"
        : "+f"(d0), "+f"(d1), "+f"(d2), "+f"(d3)
        : "r"(a0), "r"(a1), "r"(a2), "r"(a3), "r"(b0), "r"(b1));
}

// fp16 hi/lo split of two floats (low half = first value)
__device__ __forceinline__ void pack_hilo(float a, float b, uint32_t& hw, uint32_t& lw)
{
    __half2 h2 = __floats2half2_rn(a, b);
    float ra = a - __half2float(__low2half(h2));
    float rb = b - __half2float(__high2half(h2));
    __half2 l2 = __floats2half2_rn(ra, rb);
    hw = *reinterpret_cast<uint32_t*>(&h2);
    lw = *reinterpret_cast<uint32_t*>(&l2);
}

// ---------------------------------------------------------------------------
// Setup: zero state + pack fp16(hi) weights
// ---------------------------------------------------------------------------
__global__ void setup_kernel(const float* __restrict__ W1, const float* __restrict__ W2,
                             const float* __restrict__ W3, const float* __restrict__ W4)
{
    int i = blockIdx.x * blockDim.x + threadIdx.x;
    if (i < NN * HID) g_h[0][i] = 0.0f;
    if (i < NN * EF) g_agg[i] = 0.0f;
    if (i < NITER) g_tctr[i] = 0;
    if (i < WB_ELEMS) {
        const int E1 = WB1_E, E2 = E1 + WB2_E, E3 = E2 + WB2_E;
        const float* W; int e, stride, rows_real, k_real;
        if (i < E1)      { W = W1; e = i;      stride = SB1; rows_real = 96; k_real = 31; }
        else if (i < E2) { W = W2; e = i - E1; stride = SB2; rows_real = 96; k_real = 96; }
        else if (i < E3) { W = W3; e = i - E2; stride = SB2; rows_real = 96; k_real = 96; }
        else             { W = W4; e = i - E3; stride = SB2; rows_real = 11; k_real = 96; }
        int row = e / stride, c = e % stride;
        uint16_t bits = 0;
        if (row < rows_real && c < k_real) {
            __half h = __float2half_rn(W[row * k_real + c]);
            bits = *reinterpret_cast<uint16_t*>(&h);
        }
        g_wb[i] = bits;
    }
}

// ---------------------------------------------------------------------------
// One 96-wide layer, 2-pass fp16: D += (A_hi + A_lo) x B_hi^T
// Stream-tile: 64 rows; warp tile 32 rows x 48 cols (warp grid 2x2).
// ---------------------------------------------------------------------------
template<int KSTEPS, int SBB>
__device__ __forceinline__ void mma_layer(uint32_t sA, uint32_t sB,
                                          int cA_lo,
                                          int warp_m, int warp_n,
                                          int a_r, int a_k, int b_n, int b_k,
                                          float (&d)[2][6][4])
{
    uint32_t aHi = sA + (((warp_m * 32 + a_r) * SA + a_k) << 1);
    uint32_t aLo = aHi + (cA_lo << 1);
    uint32_t bBase = sB + (((warp_n * 48 + b_n) * SBB + b_k) << 1);
#pragma unroll
    for (int ks = 0; ks < KSTEPS; ks++) {
        uint32_t bb0[6], bb1[6];
#pragma unroll
        for (int j = 0; j < 3; j++) {
            uint32_t t0, t1, t2, t3;
            ldsm_x4(t0, t1, t2, t3, bBase + j * (16 * SBB * 2) + ks * 32);
            bb0[2 * j] = t0; bb1[2 * j] = t1;
            bb0[2 * j + 1] = t2; bb1[2 * j + 1] = t3;
        }
#pragma unroll
        for (int mi = 0; mi < 2; mi++) {
            uint32_t h0, h1, h2, h3, l0, l1, l2, l3;
            ldsm_x4(h0, h1, h2, h3, aHi + mi * (16 * SA * 2) + ks * 32);
            ldsm_x4(l0, l1, l2, l3, aLo + mi * (16 * SA * 2) + ks * 32);
#pragma unroll
            for (int ni = 0; ni < 6; ni++)
                mma_fp16(d[mi][ni][0], d[mi][ni][1], d[mi][ni][2], d[mi][ni][3],
                         h0, h1, h2, h3, bb0[ni], bb1[ni]);
#pragma unroll
            for (int ni = 0; ni < 6; ni++)
                mma_fp16(d[mi][ni][0], d[mi][ni][1], d[mi][ni][2], d[mi][ni][3],
                         l0, l1, l2, l3, bb0[ni], bb1[ni]);
        }
    }
}

__device__ __forceinline__ void store_act(char* smA, float (&d)[2][6][4],
                                          const float* bias, int boff,
                                          int warp_m, int warp_n, int lane)
{
    int g = lane >> 2, q = (lane & 3) * 2;
#pragma unroll
    for (int mi = 0; mi < 2; mi++) {
#pragma unroll
        for (int ni = 0; ni < 6; ni++) {
            int r0 = warp_m * 32 + mi * 16 + g;
            int c = warp_n * 48 + ni * 8 + q;
            float bz0 = bias[boff + c], bz1 = bias[boff + c + 1];
            float v0 = fmaxf(d[mi][ni][0] + bz0, 0.0f);
            float v1 = fmaxf(d[mi][ni][1] + bz1, 0.0f);
            float v2 = fmaxf(d[mi][ni][2] + bz0, 0.0f);
            float v3 = fmaxf(d[mi][ni][3] + bz1, 0.0f);
            uint32_t hw, lw;
            pack_hilo(v0, v1, hw, lw);
            *(uint32_t*)(smA + (r0 * SA + c) * 2) = hw;
            *(uint32_t*)(smA + (r0 * SA + 96 + c) * 2) = lw;
            pack_hilo(v2, v3, hw, lw);
            *(uint32_t*)(smA + ((r0 + 8) * SA + c) * 2) = hw;
            *(uint32_t*)(smA + ((r0 + 8) * SA + 96 + c) * 2) = lw;
        }
    }
}

// ---------------------------------------------------------------------------
// Persistent fused edge MLP: 4 independent 4-warp pipelines per CTA
// ---------------------------------------------------------------------------
__global__ __launch_bounds__(NTHR, 1)
void edge_kernel(int iter, int parity,
                 const float* __restrict__ edge_attr,
                 const int* __restrict__ src, const int* __restrict__ dst,
                 const float* __restrict__ b1, const float* __restrict__ b2,
                 const float* __restrict__ b3, const float* __restrict__ b4)
{
    extern __shared__ char sm[];
    const uint32_t sbase = smem_u32(sm);
    const int tid = threadIdx.x;

    float* bias = (float*)(sm + OFF_BIAS);
    __shared__ int s_tile[4];

    // stage weights + biases ONCE per CTA (all 512 threads)
    {
        const float4* gw = (const float4*)g_wb;
        float4* sw = (float4*)(sm + OFF_B1);
        for (int i = tid; i < WB_ELEMS / 8; i += NTHR) sw[i] = gw[i];
    }
    if (tid < 96) { bias[tid] = b1[tid]; bias[96 + tid] = b2[tid]; bias[192 + tid] = b3[tid]; }
    if (tid >= 96 && tid < 112) bias[288 + tid - 96] = (tid - 96 < EF) ? b4[tid - 96] : 0.0f;
    __syncthreads();

    // split into four independent streams of 4 warps
    const int qid = tid >> 7;           // 0..3
    const int qtid = tid & 127;
    const int qwid = qtid >> 5;         // 0..3
    const int lane = qtid & 31;
    const int bar_id = 1 + qid;

    const int warp_m = qwid & 1;        // 2 x 32 rows
    const int warp_n = qwid >> 1;       // 2 x 48 cols
    const int am = lane >> 3;
    const int a_r = ((am & 1) << 3) | (lane & 7);
    const int a_k = (am >> 1) << 3;
    const int b_n = ((am >> 1) << 3) | (lane & 7);
    const int b_k = (am & 1) << 3;

    char* smA = sm + OFF_A + qid * (EST * SA * 2);
    const uint32_t sbA = sbase + OFF_A + qid * (EST * SA * 2);
    int* ids = (int*)(sm + OFF_IDS) + qid * 128;

    while (true) {
        if (qtid == 0) s_tile[qid] = atomicAdd(&g_tctr[iter], 1);
        barq(bar_id);                    // also: stream done with previous tile
        const int tile = s_tile[qid];
        if (tile >= TILES4) break;
        const int ebase = tile * EST;

        ids[qtid] = (qtid < EST) ? src[ebase + qtid] : dst[ebase + qtid - EST];
        barq(bar_id);

        // gather: 2 threads per row (cols 0..15 / 16..31), hi + lo
        {
            int row = qtid >> 1, hf = qtid & 1;
            float x[16];
            if (hf == 0) {
                const float* hs = g_h[parity] + (size_t)ids[row] * HID;
                const float* hd = g_h[parity] + (size_t)ids[EST + row] * HID;
#pragma unroll
                for (int i = 0; i < HID; i++) x[i] = hs[i];
#pragma unroll
                for (int i = 0; i < 6; i++) x[HID + i] = hd[i];
            } else {
                const float* hd = g_h[parity] + (size_t)ids[EST + row] * HID;
#pragma unroll
                for (int i = 0; i < 4; i++) x[i] = hd[6 + i];
#pragma unroll
                for (int i = 0; i < EF; i++)
                    x[4 + i] = edge_attr[(size_t)(ebase + row) * EF + i];
                x[15] = 0.0f;
            }
            int cb = hf * 16;
#pragma unroll
            for (int p = 0; p < 8; p++) {
                uint32_t hw, lw;
                pack_hilo(x[2 * p], x[2 * p + 1], hw, lw);
                *(uint32_t*)(smA + (row * SA + cb + 2 * p) * 2) = hw;
                *(uint32_t*)(smA + (row * SA + 32 + cb + 2 * p) * 2) = lw;
            }
        }
        barq(bar_id);

        float d[2][6][4];

        // ---- Layer 1 (K=32 incl pad, A lo at col 32)
#pragma unroll
        for (int mi = 0; mi < 2; mi++)
#pragma unroll
            for (int ni = 0; ni < 6; ni++)
#pragma unroll
                for (int v = 0; v < 4; v++) d[mi][ni][v] = 0.0f;
        mma_layer<2, SB1>(sbA, sbase + OFF_B1, 32,
                          warp_m, warp_n, a_r, a_k, b_n, b_k, d);
        barq(bar_id);
        store_act(smA, d, bias, 0, warp_m, warp_n, lane);
        barq(bar_id);

        // ---- Layer 2
#pragma unroll
        for (int mi = 0; mi < 2; mi++)
#pragma unroll
            for (int ni = 0; ni < 6; ni++)
#pragma unroll
                for (int v = 0; v < 4; v++) d[mi][ni][v] = 0.0f;
        mma_layer<6, SB2>(sbA, sbase + OFF_B2, 96,
                          warp_m, warp_n, a_r, a_k, b_n, b_k, d);
        barq(bar_id);
        store_act(smA, d, bias, 96, warp_m, warp_n, lane);
        barq(bar_id);

        // ---- Layer 3
#pragma unroll
        for (int mi = 0; mi < 2; mi++)
#pragma unroll
            for (int ni = 0; ni < 6; ni++)
#pragma unroll
                for (int v = 0; v < 4; v++) d[mi][ni][v] = 0.0f;
        mma_layer<6, SB2>(sbA, sbase + OFF_B3, 96,
                          warp_m, warp_n, a_r, a_k, b_n, b_k, d);
        barq(bar_id);
        store_act(smA, d, bias, 192, warp_m, warp_n, lane);
        barq(bar_id);

        // ---- Layer 4: N=16 (11 real); warp_n covers n8 tile 0/1
        float d4[2][4];
#pragma unroll
        for (int mi = 0; mi < 2; mi++)
#pragma unroll
            for (int v = 0; v < 4; v++) d4[mi][v] = 0.0f;
        {
            const int b4n = (lane & 7);
            const int b4k = ((lane >> 3) & 1) * 8;
            uint32_t aHi = sbA + (((warp_m * 32 + a_r) * SA + a_k) << 1);
            uint32_t aLo = aHi + (96 << 1);
            uint32_t bBase = sbase + OFF_B4 + (((warp_n * 8 + b4n) * SB2 + b4k) << 1);
#pragma unroll
            for (int ks = 0; ks < 6; ks++) {
                uint32_t bb0, bb1;
                ldsm_x2(bb0, bb1, bBase + ks * 32);
#pragma unroll
                for (int mi = 0; mi < 2; mi++) {
                    uint32_t h0, h1, h2, h3, l0, l1, l2, l3;
                    ldsm_x4(h0, h1, h2, h3, aHi + mi * (16 * SA * 2) + ks * 32);
                    ldsm_x4(l0, l1, l2, l3, aLo + mi * (16 * SA * 2) + ks * 32);
                    mma_fp16(d4[mi][0], d4[mi][1], d4[mi][2], d4[mi][3],
                             h0, h1, h2, h3, bb0, bb1);
                    mma_fp16(d4[mi][0], d4[mi][1], d4[mi][2], d4[mi][3],
                             l0, l1, l2, l3, bb0, bb1);
                }
            }
        }

        // scatter-add
        {
            int g = lane >> 2, q = (lane & 3) * 2;
            int c = warp_n * 8 + q;
            float bz0 = (c < EF) ? bias[288 + c] : 0.0f;
            float bz1 = (c + 1 < EF) ? bias[288 + c + 1] : 0.0f;
#pragma unroll
            for (int mi = 0; mi < 2; mi++) {
                int r = warp_m * 32 + mi * 16 + g;
                int dn0 = ids[EST + r];
                int dn1 = ids[EST + r + 8];
                if (c < EF) {
                    atomicAdd(&g_agg[(size_t)dn0 * EF + c], d4[mi][0] + bz0);
                    atomicAdd(&g_agg[(size_t)dn1 * EF + c], d4[mi][2] + bz0);
                }
                if (c + 1 < EF) {
                    atomicAdd(&g_agg[(size_t)dn0 * EF + c + 1], d4[mi][1] + bz1);
                    atomicAdd(&g_agg[(size_t)dn1 * EF + c + 1], d4[mi][3] + bz1);
                }
            }
        }
    }
}

// ---------------------------------------------------------------------------
// GRU cell + output head; zeroes g_agg for next iter.
// ---------------------------------------------------------------------------
__global__ void gru_kernel(int parity,
                           const float* __restrict__ node_in,
                           const float* __restrict__ wih,
                           const float* __restrict__ whh,
                           const float* __restrict__ bih,
                           const float* __restrict__ bhh,
                           const float* __restrict__ fw,
                           const float* __restrict__ fb,
                           float* __restrict__ out)
{
    __shared__ float s[600 + 300 + 30 + 30 + 20 + 2];
    int tid = threadIdx.x;
    for (int i = tid; i < 600; i += blockDim.x) s[i] = wih[i];
    for (int i = tid; i < 300; i += blockDim.x) s[600 + i] = whh[i];
    for (int i = tid; i < 30; i += blockDim.x) { s[900 + i] = bih[i]; s[930 + i] = bhh[i]; }
    for (int i = tid; i < 20; i += blockDim.x) s[960 + i] = fw[i];
    for (int i = tid; i < 2; i += blockDim.x) s[980 + i] = fb[i];
    __syncthreads();

    int n = blockIdx.x * blockDim.x + tid;
    if (n >= NN) return;

    const float* __restrict__ hp = g_h[parity] + n * HID;
    float* __restrict__ hn = g_h[1 - parity] + n * HID;

    float x[20], hv[HID];
#pragma unroll
    for (int i = 0; i < EF; i++) { x[i] = g_agg[n * EF + i]; g_agg[n * EF + i] = 0.0f; }
#pragma unroll
    for (int i = 0; i < NIN; i++) x[EF + i] = node_in[n * NIN + i];
#pragma unroll
    for (int i = 0; i < HID; i++) hv[i] = hp[i];

    float gi[30], gh[30];
#pragma unroll
    for (int g = 0; g < 30; g++) {
        float a = s[900 + g];
#pragma unroll
        for (int k = 0; k < 20; k++) a = fmaf(s[g * 20 + k], x[k], a);
        gi[g] = a;
        float b = s[930 + g];
#pragma unroll
        for (int k = 0; k < 10; k++) b = fmaf(s[600 + g * 10 + k], hv[k], b);
        gh[g] = b;
    }

    float hnew[HID];
#pragma unroll
    for (int i = 0; i < HID; i++) {
        float r = 1.0f / (1.0f + expf(-(gi[i] + gh[i])));
        float z = 1.0f / (1.0f + expf(-(gi[10 + i] + gh[10 + i])));
        float nval = tanhf(gi[20 + i] + r * gh[20 + i]);
        float hni = (1.0f - z) * nval + z * hv[i];
        hnew[i] = hni;
        hn[i] = hni;
    }

#pragma unroll
    for (int o = 0; o < 2; o++) {
        float a = s[980 + o];
#pragma unroll
        for (int k = 0; k < HID; k++) a = fmaf(s[960 + o * 10 + k], hnew[k], a);
        out[n * 2 + o] = a;
    }
}

// ---------------------------------------------------------------------------
// Launch
// ---------------------------------------------------------------------------
extern "C" void kernel_launch(void* const* d_in, const int* in_sizes, int n_in,
                              void* d_out, int out_size)
{
    const float* node_in   = (const float*)d_in[0];
    const float* edge_attr = (const float*)d_in[1];
    const float* W1 = (const float*)d_in[2];  const float* b1 = (const float*)d_in[3];
    const float* W2 = (const float*)d_in[4];  const float* b2 = (const float*)d_in[5];
    const float* W3 = (const float*)d_in[6];  const float* b3 = (const float*)d_in[7];
    const float* W4 = (const float*)d_in[8];  const float* b4 = (const float*)d_in[9];
    const float* wih = (const float*)d_in[10]; const float* whh = (const float*)d_in[11];
    const float* bih = (const float*)d_in[12]; const float* bhh = (const float*)d_in[13];
    const float* fw  = (const float*)d_in[14]; const float* fb  = (const float*)d_in[15];
    const int* src = (const int*)d_in[16];
    const int* dst = (const int*)d_in[17];
    float* out = (float*)d_out;

    cudaFuncSetAttribute(edge_kernel,
                         cudaFuncAttributeMaxDynamicSharedMemorySize, SMEM_REQ);

    setup_kernel<<<(NN * EF + 255) / 256, 256>>>(W1, W2, W3, W4);

    for (int t = 0; t < NITER; t++) {
        int p = t & 1;
        edge_kernel<<<NCTA, NTHR, SMEM_REQ>>>(t, p, edge_attr, src, dst,
                                              b1, b2, b3, b4);
        gru_kernel<<<(NN + 127) / 128, 128>>>(p, node_in, wih, whh, bih, bhh,
                                              fw, fb, out + (size_t)t * NN * 2);
    }
}

// round 14
// speedup vs baseline: 2.3718x; 1.2655x over previous
#include <cuda_runtime.h>
#include <cuda_fp16.h>
#include <math.h>
#include <stdint.h>

// Problem constants
#define NN     20000
#define NE     320000
#define HID    10
#define NIN    9
#define EF     11
#define NITER  7
#define EWT    16        // edges per warp-tile
#define TILESW (NE/EWT)  // 20000
#define NTHR   384       // 12 warps, each an independent pipeline
#define NWARP  (NTHR/32)
#define NCTA   152       // persistent CTAs

// ---------------- smem layout (byte offsets) -------------------------------
#define SB1       40
#define SB2       104
#define SA1       72     // A1 stride (elements): 144B rows -> conflict-free ldsm
#define B1_BYTES  (96*SB1*2)             // 7680
#define B2_BYTES  (96*SB2*2)             // 19968
#define B4_BYTES  (16*SB2*2)             // 3328
#define OFF_B1    0
#define OFF_B2    (OFF_B1 + B1_BYTES)    // 7680
#define OFF_B3    (OFF_B2 + B2_BYTES)    // 27648
#define OFF_B4    (OFF_B3 + B2_BYTES)    // 47616
#define OFF_BIAS  (OFF_B4 + B4_BYTES)    // 50944 (304 floats)
#define OFF_A1    (OFF_BIAS + 304*4)     // 52160
#define A1W_BYTES (EWT*SA1*2)            // 2304 per warp
#define OFF_IDS   (OFF_A1 + NWARP*A1W_BYTES)   // 79808
#define SMEM_REQ  (OFF_IDS + NWARP*32*4)       // 81344

// Weight blob (fp16 hi only): B1|B2|B3|B4 (same layout as before)
#define WB1_E   (96*SB1)
#define WB2_E   (96*SB2)
#define WB_ELEMS (WB1_E + 2*WB2_E + 16*SB2)   // 25472
__device__ __align__(16) uint16_t g_wb[WB_ELEMS];
__device__ float g_h[2][NN * HID];
__device__ float g_agg[NN * EF];
__device__ int   g_tctr[NITER];

// ------------------------------ helpers ------------------------------------
__device__ __forceinline__ uint32_t smem_u32(const void* p)
{
    uint32_t a;
    asm("{ .reg .u64 t; cvta.to.shared.u64 t, %1; cvt.u32.u64 %0, t; }"
        : "=r"(a) : "l"(p));
    return a;
}

__device__ __forceinline__ void ldsm_x4(uint32_t& r0, uint32_t& r1,
                                        uint32_t& r2, uint32_t& r3, uint32_t a)
{
    asm volatile("ldmatrix.sync.aligned.m8n8.x4.shared.b16 {%0,%1,%2,%3}, [%4];"
                 : "=r"(r0), "=r"(r1), "=r"(r2), "=r"(r3) : "r"(a));
}

__device__ __forceinline__ void mma_fp16(float* d,
                                         uint32_t a0, uint32_t a1, uint32_t a2,
                                         uint32_t a3, uint32_t b0, uint32_t b1)
{
    asm volatile(
        "mma.sync.aligned.m16n8k16.row.col.f32.f16.f16.f32 "
        "{%0,%1,%2,%3},{%4,%5,%6,%7},{%8,%9},{%0,%1,%2,%3};"
        : "+f"(d[0]), "+f"(d[1]), "+f"(d[2]), "+f"(d[3])
        : "r"(a0), "r"(a1), "r"(a2), "r"(a3), "r"(b0), "r"(b1));
}

// fp16 hi/lo split of two floats (low half = first value)
__device__ __forceinline__ void pack_hilo(float a, float b, uint32_t& hw, uint32_t& lw)
{
    __half2 h2 = __floats2half2_rn(a, b);
    float ra = a - __half2float(__low2half(h2));
    float rb = b - __half2float(__high2half(h2));
    __half2 l2 = __floats2half2_rn(ra, rb);
    hw = *reinterpret_cast<uint32_t*>(&h2);
    lw = *reinterpret_cast<uint32_t*>(&l2);
}

// ---------------------------------------------------------------------------
// Setup: zero state + pack fp16(hi) weights
// ---------------------------------------------------------------------------
__global__ void setup_kernel(const float* __restrict__ W1, const float* __restrict__ W2,
                             const float* __restrict__ W3, const float* __restrict__ W4)
{
    int i = blockIdx.x * blockDim.x + threadIdx.x;
    if (i < NN * HID) g_h[0][i] = 0.0f;
    if (i < NN * EF) g_agg[i] = 0.0f;
    if (i < NITER) g_tctr[i] = 0;
    if (i < WB_ELEMS) {
        const int E1 = WB1_E, E2 = E1 + WB2_E, E3 = E2 + WB2_E;
        const float* W; int e, stride, rows_real, k_real;
        if (i < E1)      { W = W1; e = i;      stride = SB1; rows_real = 96; k_real = 31; }
        else if (i < E2) { W = W2; e = i - E1; stride = SB2; rows_real = 96; k_real = 96; }
        else if (i < E3) { W = W3; e = i - E2; stride = SB2; rows_real = 96; k_real = 96; }
        else             { W = W4; e = i - E3; stride = SB2; rows_real = 11; k_real = 96; }
        int row = e / stride, c = e % stride;
        uint16_t bits = 0;
        if (row < rows_real && c < k_real) {
            __half h = __float2half_rn(W[row * k_real + c]);
            bits = *reinterpret_cast<uint16_t*>(&h);
        }
        g_wb[i] = bits;
    }
}

// ---------------------------------------------------------------------------
// Persistent warp-autonomous edge MLP: each warp owns 16 edges end-to-end.
// Activations forwarded in registers (D-frag == next A-frag identity).
// ---------------------------------------------------------------------------
__global__ __launch_bounds__(NTHR, 1)
void edge_kernel(int iter, int parity,
                 const float* __restrict__ edge_attr,
                 const int* __restrict__ src, const int* __restrict__ dst,
                 const float* __restrict__ b1, const float* __restrict__ b2,
                 const float* __restrict__ b3, const float* __restrict__ b4)
{
    extern __shared__ char sm[];
    const uint32_t sbase = smem_u32(sm);
    const int tid = threadIdx.x;
    const int wid = tid >> 5, lane = tid & 31;

    float* biasf = (float*)(sm + OFF_BIAS);

    // stage weights + biases ONCE per CTA
    {
        const float4* gw = (const float4*)g_wb;
        float4* sw = (float4*)(sm + OFF_B1);
        for (int i = tid; i < WB_ELEMS / 8; i += NTHR) sw[i] = gw[i];
    }
    if (tid < 96) { biasf[tid] = b1[tid]; biasf[96 + tid] = b2[tid]; biasf[192 + tid] = b3[tid]; }
    if (tid >= 96 && tid < 112) biasf[288 + tid - 96] = (tid - 96 < EF) ? b4[tid - 96] : 0.0f;
    __syncthreads();

    // lane-derived fragment coordinates
    const int am = lane >> 3;
    const int a_r = ((am & 1) << 3) | (lane & 7);
    const int a_k = (am >> 1) << 3;
    const int b_n = ((am >> 1) << 3) | (lane & 7);
    const int b_k = (am & 1) << 3;
    const int q2 = (lane & 3) * 2;
    const int g8 = lane >> 2;

    char* smA1 = sm + OFF_A1 + wid * A1W_BYTES;
    const uint32_t sbA1 = sbase + OFF_A1 + wid * A1W_BYTES;
    int* wids = (int*)(sm + OFF_IDS) + wid * 32;
    const float* __restrict__ hbase = g_h[parity];

    while (true) {
        int t0c;
        if (lane == 0) t0c = atomicAdd(&g_tctr[iter], 1);
        const int tile = __shfl_sync(0xffffffffu, t0c, 0);
        if (tile >= TILESW) break;
        const int ebase = tile * EWT;

        // ---- ids (per-warp)
        wids[lane] = (lane < EWT) ? src[ebase + lane] : dst[ebase + lane - EWT];
        __syncwarp();

        // ---- gather 16 edges x 31 cols -> A1 [16 x (hi32|lo32)] fp16
        {
            int row = lane >> 1, hf = lane & 1;
            float x[16];
            if (hf == 0) {
                const float* hs = hbase + (size_t)wids[row] * HID;
                const float* hd = hbase + (size_t)wids[EWT + row] * HID;
#pragma unroll
                for (int i = 0; i < HID; i++) x[i] = hs[i];
#pragma unroll
                for (int i = 0; i < 6; i++) x[HID + i] = hd[i];
            } else {
                const float* hd = hbase + (size_t)wids[EWT + row] * HID;
#pragma unroll
                for (int i = 0; i < 4; i++) x[i] = hd[6 + i];
#pragma unroll
                for (int i = 0; i < EF; i++)
                    x[4 + i] = edge_attr[(size_t)(ebase + row) * EF + i];
                x[15] = 0.0f;
            }
            uint32_t hh[8], ll[8];
#pragma unroll
            for (int p = 0; p < 8; p++) pack_hilo(x[2 * p], x[2 * p + 1], hh[p], ll[p]);
            int cb = hf * 16;
            *(uint4*)(smA1 + (row * SA1 + cb) * 2)      = make_uint4(hh[0], hh[1], hh[2], hh[3]);
            *(uint4*)(smA1 + (row * SA1 + cb + 8) * 2)  = make_uint4(hh[4], hh[5], hh[6], hh[7]);
            *(uint4*)(smA1 + (row * SA1 + 32 + cb) * 2) = make_uint4(ll[0], ll[1], ll[2], ll[3]);
            *(uint4*)(smA1 + (row * SA1 + 32 + cb + 8) * 2) = make_uint4(ll[4], ll[5], ll[6], ll[7]);
        }
        __syncwarp();

        float d[12][4];

        // ---- Layer 1: A from smem (K=32 hi + 32 lo), B1
        {
#pragma unroll
            for (int j = 0; j < 12; j++) {
                float2 bp = *(float2*)(biasf + 8 * j + q2);
                d[j][0] = bp.x; d[j][1] = bp.y; d[j][2] = bp.x; d[j][3] = bp.y;
            }
            uint32_t a1h[2][4], a1l[2][4];
            const uint32_t aAddr = sbA1 + (a_r * SA1 + a_k) * 2;
#pragma unroll
            for (int ks = 0; ks < 2; ks++) {
                ldsm_x4(a1h[ks][0], a1h[ks][1], a1h[ks][2], a1h[ks][3], aAddr + ks * 32);
                ldsm_x4(a1l[ks][0], a1l[ks][1], a1l[ks][2], a1l[ks][3], aAddr + 64 + ks * 32);
            }
#pragma unroll
            for (int j2 = 0; j2 < 6; j2++) {
#pragma unroll
                for (int ks = 0; ks < 2; ks++) {
                    uint32_t t0, t1, t2, t3;
                    ldsm_x4(t0, t1, t2, t3,
                            sbase + OFF_B1 + ((j2 * 16 + b_n) * SB1 + ks * 16 + b_k) * 2);
                    mma_fp16(d[2 * j2],     a1h[ks][0], a1h[ks][1], a1h[ks][2], a1h[ks][3], t0, t1);
                    mma_fp16(d[2 * j2 + 1], a1h[ks][0], a1h[ks][1], a1h[ks][2], a1h[ks][3], t2, t3);
                    mma_fp16(d[2 * j2],     a1l[ks][0], a1l[ks][1], a1l[ks][2], a1l[ks][3], t0, t1);
                    mma_fp16(d[2 * j2 + 1], a1l[ks][0], a1l[ks][1], a1l[ks][2], a1l[ks][3], t2, t3);
                }
            }
        }

        uint32_t af[24], al[24];

        // ---- convert D -> A frags (relu + fp16 hi/lo), in registers
#pragma unroll
        for (int j = 0; j < 12; j++) {
            float v0 = fmaxf(d[j][0], 0.0f), v1 = fmaxf(d[j][1], 0.0f);
            float v2 = fmaxf(d[j][2], 0.0f), v3 = fmaxf(d[j][3], 0.0f);
            pack_hilo(v0, v1, af[2 * j], al[2 * j]);
            pack_hilo(v2, v3, af[2 * j + 1], al[2 * j + 1]);
        }

        // ---- Layers 2 and 3: A from registers, B from smem
#pragma unroll 1
        for (int L = 0; L < 2; L++) {
            const uint32_t bOff = (L == 0) ? OFF_B2 : OFF_B3;
            const int boff = (L == 0) ? 96 : 192;
#pragma unroll
            for (int j = 0; j < 12; j++) {
                float2 bp = *(float2*)(biasf + boff + 8 * j + q2);
                d[j][0] = bp.x; d[j][1] = bp.y; d[j][2] = bp.x; d[j][3] = bp.y;
            }
#pragma unroll
            for (int j2 = 0; j2 < 6; j2++) {
#pragma unroll
                for (int ks = 0; ks < 6; ks++) {
                    uint32_t t0, t1, t2, t3;
                    ldsm_x4(t0, t1, t2, t3,
                            sbase + bOff + ((j2 * 16 + b_n) * SB2 + ks * 16 + b_k) * 2);
                    mma_fp16(d[2 * j2],     af[4 * ks], af[4 * ks + 1], af[4 * ks + 2], af[4 * ks + 3], t0, t1);
                    mma_fp16(d[2 * j2 + 1], af[4 * ks], af[4 * ks + 1], af[4 * ks + 2], af[4 * ks + 3], t2, t3);
                    mma_fp16(d[2 * j2],     al[4 * ks], al[4 * ks + 1], al[4 * ks + 2], al[4 * ks + 3], t0, t1);
                    mma_fp16(d[2 * j2 + 1], al[4 * ks], al[4 * ks + 1], al[4 * ks + 2], al[4 * ks + 3], t2, t3);
                }
            }
#pragma unroll
            for (int j = 0; j < 12; j++) {
                float v0 = fmaxf(d[j][0], 0.0f), v1 = fmaxf(d[j][1], 0.0f);
                float v2 = fmaxf(d[j][2], 0.0f), v3 = fmaxf(d[j][3], 0.0f);
                pack_hilo(v0, v1, af[2 * j], al[2 * j]);
                pack_hilo(v2, v3, af[2 * j + 1], al[2 * j + 1]);
            }
        }

        // ---- Layer 4: N=16 (11 real), A from registers
        float d4[2][4];
#pragma unroll
        for (int nt = 0; nt < 2; nt++) {
            float2 bp = *(float2*)(biasf + 288 + 8 * nt + q2);
            d4[nt][0] = bp.x; d4[nt][1] = bp.y; d4[nt][2] = bp.x; d4[nt][3] = bp.y;
        }
#pragma unroll
        for (int ks = 0; ks < 6; ks++) {
            uint32_t t0, t1, t2, t3;
            ldsm_x4(t0, t1, t2, t3,
                    sbase + OFF_B4 + (b_n * SB2 + ks * 16 + b_k) * 2);
            mma_fp16(d4[0], af[4 * ks], af[4 * ks + 1], af[4 * ks + 2], af[4 * ks + 3], t0, t1);
            mma_fp16(d4[1], af[4 * ks], af[4 * ks + 1], af[4 * ks + 2], af[4 * ks + 3], t2, t3);
            mma_fp16(d4[0], al[4 * ks], al[4 * ks + 1], al[4 * ks + 2], al[4 * ks + 3], t0, t1);
            mma_fp16(d4[1], al[4 * ks], al[4 * ks + 1], al[4 * ks + 2], al[4 * ks + 3], t2, t3);
        }

        // ---- scatter-add to destination nodes
        {
            int dn0 = wids[EWT + g8];
            int dn1 = wids[EWT + g8 + 8];
#pragma unroll
            for (int nt = 0; nt < 2; nt++) {
                int c = nt * 8 + q2;
                if (c < EF) {
                    atomicAdd(&g_agg[(size_t)dn0 * EF + c], d4[nt][0]);
                    atomicAdd(&g_agg[(size_t)dn1 * EF + c], d4[nt][2]);
                }
                if (c + 1 < EF) {
                    atomicAdd(&g_agg[(size_t)dn0 * EF + c + 1], d4[nt][1]);
                    atomicAdd(&g_agg[(size_t)dn1 * EF + c + 1], d4[nt][3]);
                }
            }
        }
        __syncwarp();   // all lanes done with wids/A1 before next tile reuses them
    }
}

// ---------------------------------------------------------------------------
// GRU cell + output head; zeroes g_agg for next iter.
// ---------------------------------------------------------------------------
__global__ void gru_kernel(int parity,
                           const float* __restrict__ node_in,
                           const float* __restrict__ wih,
                           const float* __restrict__ whh,
                           const float* __restrict__ bih,
                           const float* __restrict__ bhh,
                           const float* __restrict__ fw,
                           const float* __restrict__ fb,
                           float* __restrict__ out)
{
    __shared__ float s[600 + 300 + 30 + 30 + 20 + 2];
    int tid = threadIdx.x;
    for (int i = tid; i < 600; i += blockDim.x) s[i] = wih[i];
    for (int i = tid; i < 300; i += blockDim.x) s[600 + i] = whh[i];
    for (int i = tid; i < 30; i += blockDim.x) { s[900 + i] = bih[i]; s[930 + i] = bhh[i]; }
    for (int i = tid; i < 20; i += blockDim.x) s[960 + i] = fw[i];
    for (int i = tid; i < 2; i += blockDim.x) s[980 + i] = fb[i];
    __syncthreads();

    int n = blockIdx.x * blockDim.x + tid;
    if (n >= NN) return;

    const float* __restrict__ hp = g_h[parity] + n * HID;
    float* __restrict__ hn = g_h[1 - parity] + n * HID;

    float x[20], hv[HID];
#pragma unroll
    for (int i = 0; i < EF; i++) { x[i] = g_agg[n * EF + i]; g_agg[n * EF + i] = 0.0f; }
#pragma unroll
    for (int i = 0; i < NIN; i++) x[EF + i] = node_in[n * NIN + i];
#pragma unroll
    for (int i = 0; i < HID; i++) hv[i] = hp[i];

    float gi[30], gh[30];
#pragma unroll
    for (int g = 0; g < 30; g++) {
        float a = s[900 + g];
#pragma unroll
        for (int k = 0; k < 20; k++) a = fmaf(s[g * 20 + k], x[k], a);
        gi[g] = a;
        float b = s[930 + g];
#pragma unroll
        for (int k = 0; k < 10; k++) b = fmaf(s[600 + g * 10 + k], hv[k], b);
        gh[g] = b;
    }

    float hnew[HID];
#pragma unroll
    for (int i = 0; i < HID; i++) {
        float r = 1.0f / (1.0f + expf(-(gi[i] + gh[i])));
        float z = 1.0f / (1.0f + expf(-(gi[10 + i] + gh[10 + i])));
        float nval = tanhf(gi[20 + i] + r * gh[20 + i]);
        float hni = (1.0f - z) * nval + z * hv[i];
        hnew[i] = hni;
        hn[i] = hni;
    }

#pragma unroll
    for (int o = 0; o < 2; o++) {
        float a = s[980 + o];
#pragma unroll
        for (int k = 0; k < HID; k++) a = fmaf(s[960 + o * 10 + k], hnew[k], a);
        out[n * 2 + o] = a;
    }
}

// ---------------------------------------------------------------------------
// Launch
// ---------------------------------------------------------------------------
extern "C" void kernel_launch(void* const* d_in, const int* in_sizes, int n_in,
                              void* d_out, int out_size)
{
    const float* node_in   = (const float*)d_in[0];
    const float* edge_attr = (const float*)d_in[1];
    const float* W1 = (const float*)d_in[2];  const float* b1 = (const float*)d_in[3];
    const float* W2 = (const float*)d_in[4];  const float* b2 = (const float*)d_in[5];
    const float* W3 = (const float*)d_in[6];  const float* b3 = (const float*)d_in[7];
    const float* W4 = (const float*)d_in[8];  const float* b4 = (const float*)d_in[9];
    const float* wih = (const float*)d_in[10]; const float* whh = (const float*)d_in[11];
    const float* bih = (const float*)d_in[12]; const float* bhh = (const float*)d_in[13];
    const float* fw  = (const float*)d_in[14]; const float* fb  = (const float*)d_in[15];
    const int* src = (const int*)d_in[16];
    const int* dst = (const int*)d_in[17];
    float* out = (float*)d_out;

    cudaFuncSetAttribute(edge_kernel,
                         cudaFuncAttributeMaxDynamicSharedMemorySize, SMEM_REQ);

    setup_kernel<<<(NN * EF + 255) / 256, 256>>>(W1, W2, W3, W4);

    for (int t = 0; t < NITER; t++) {
        int p = t & 1;
        edge_kernel<<<NCTA, NTHR, SMEM_REQ>>>(t, p, edge_attr, src, dst,
                                              b1, b2, b3, b4);
        gru_kernel<<<(NN + 127) / 128, 128>>>(p, node_in, wih, whh, bih, bhh,
                                              fw, fb, out + (size_t)t * NN * 2);
    }
}